// round 6
// baseline (speedup 1.0000x reference)
#include <cuda_runtime.h>
#include <math.h>

// MTPhysicsLoss: 1D MT forward + misfit loss, single fused kernel.
//
// Projective recursion (no division on chain):
//   P' = A*P + B*Q ; Q' = C*P + A*Q   (complex), Z = P/Q
//   A = Zj(1-E), B = 2a^2 i (1+E), C = (1+E), Zj = a(1+i), a = s*sqrt(rho/2)
//   E = e^{-x}(cos x - i sin x), x = s*sqrt(2)*t/sqrt(rho), s = sqrt(omega*mu)
//
// fma-pipe-bound (FFMA rt_SMSP=2, 1 warp/SMSP): update done with packed
// fma.rn.f32x2 (FFMA2, 2 FLOPs per pipe slot). Pack/swap MOVs ride the alu pipe.
// Final reduction fused via last-block-done (atomicInc wrap => graph-replay safe,
// fixed-order sum => deterministic).

#define NZ   256
#define NF   16384
#define BLK  128
#define NBLK (NF / BLK)   // 128 blocks

#define MU_F        1.2566370614359173e-6f
#define TWO_PI_F    6.283185307179586f
#define INV_SQRT2_F 0.7071067811865476f
#define SQRT2_F     1.4142135623730951f
#define RAD2DEG_F   57.29577951308232f

__device__ float g_part_rhoa[NBLK];
__device__ float g_part_phase[NBLK];
__device__ unsigned int g_count = 0;

typedef unsigned long long u64;

__device__ __forceinline__ float fast_rcp(float x) {
    float r; asm("rcp.approx.f32 %0, %1;" : "=f"(r) : "f"(x)); return r;
}
__device__ __forceinline__ u64 pk(float lo, float hi) {
    u64 r; asm("mov.b64 %0, {%1, %2};" : "=l"(r) : "f"(lo), "f"(hi)); return r;
}
__device__ __forceinline__ void upk(u64 v, float& lo, float& hi) {
    asm("mov.b64 {%0, %1}, %2;" : "=f"(lo), "=f"(hi) : "l"(v));
}
__device__ __forceinline__ u64 fma2(u64 a, u64 b, u64 c) {
    u64 d; asm("fma.rn.f32x2 %0, %1, %2, %3;" : "=l"(d) : "l"(a), "l"(b), "l"(c)); return d;
}
__device__ __forceinline__ u64 mul2(u64 a, u64 b) {
    u64 d; asm("mul.rn.f32x2 %0, %1, %2;" : "=l"(d) : "l"(a), "l"(b)); return d;
}

__global__ __launch_bounds__(BLK, 1)
void mt_fused_kernel(const float* __restrict__ rho,
                     const float* __restrict__ thick,
                     const float* __restrict__ freq,
                     const float* __restrict__ obs_rhoa,
                     const float* __restrict__ obs_phase,
                     float* __restrict__ out) {
    __shared__ float sh_h[NZ];       // sqrt(rho_j)/sqrt(2)     -> a = s*h
    __shared__ float sh_g[NZ - 1];   // sqrt(2)*t_j/sqrt(rho_j) -> x = s*g

    const int tid = threadIdx.x;

    #pragma unroll
    for (int j = tid; j < NZ; j += BLK) {
        float sr = sqrtf(rho[j]);
        sh_h[j] = sr * INV_SQRT2_F;
        if (j < NZ - 1) sh_g[j] = SQRT2_F * thick[j] * fast_rcp(sr);
    }
    __syncthreads();

    const int fi = blockIdx.x * BLK + tid;
    const float omu = TWO_PI_F * freq[fi] * MU_F;
    const float s   = sqrtf(omu);

    // Homogeneous state: P = Z0 = a0(1+i), Q = 1. Packed (re, im) + swapped copies.
    const float a0 = s * sh_h[NZ - 1];
    u64 vP  = pk(a0, a0);
    u64 vPs = pk(a0, a0);
    u64 vQ  = pk(1.0f, 0.0f);
    u64 vQs = pk(0.0f, 1.0f);

    // 255 steps, 51 groups of 5, exact power-of-two renorm per group.
    for (int base = NZ - 2; base >= 4; base -= 5) {
        #pragma unroll
        for (int k = 0; k < 5; ++k) {
            const int j = base - k;
            // ---- scalar coefficients (freq+layer only) ----
            float a = s * sh_h[j];
            float x = s * sh_g[j];
            float e = __expf(-x);
            float sx, cx; __sincosf(x, &sx, &cx);
            float ecx = e * cx;          // Re(E)
            float esx = e * sx;          // -Im(E)
            float vr  = 1.0f + ecx;      // Re(C)=Re(1+E), Im(C)=-esx
            float w   = 1.0f - ecx;
            float Ar  = a * (w - esx);   // A = Zj(1-E)
            float Ai  = a * (w + esx);
            float a22 = 2.0f * (a * a);
            float Br  = a22 * esx;       // B = 2a^2 i (1+E)
            float Bi  = a22 * vr;

            // ---- packed broadcast / swap-negate coefficient layouts (alu pipe) ----
            u64 cA  = pk(Ar,  Ar);
            u64 cAn = pk(-Ai, Ai);
            u64 cB  = pk(Br,  Br);
            u64 cBn = pk(-Bi, Bi);
            u64 cV  = pk(vr,  vr);
            u64 cVn = pk(esx, -esx);     // (-vi, vi), vi = -esx

            // ---- packed update: 8 f32x2 ops instead of 16 scalar FFMAs ----
            u64 nP = fma2(cA, vP, fma2(cAn, vPs, fma2(cB, vQ, mul2(cBn, vQs))));
            u64 nQ = fma2(cV, vP, fma2(cVn, vPs, fma2(cA, vQ, mul2(cAn, vQs))));

            float pr, pi, qr, qi;
            upk(nP, pr, pi); upk(nQ, qr, qi);
            vP = nP; vPs = pk(pi, pr);
            vQ = nQ; vQs = pk(qi, qr);
        }
        // Exact power-of-two renorm (no rounding): scale = 2^{-exponent(|Qr|+|Qi|)}
        float qr, qi; upk(vQ, qr, qi);
        float m = fabsf(qr) + fabsf(qi);
        int ebits = __float_as_int(m) & 0x7F800000;
        float scale = __int_as_float(0x7F000000 - ebits);
        u64 cS = pk(scale, scale);
        vP = mul2(vP, cS); vPs = mul2(vPs, cS);
        vQ = mul2(vQ, cS); vQs = mul2(vQs, cS);
    }

    // Misfits: Z = P/Q. log10|Z|^2 = log10|P|^2 - log10|Q|^2; phase from P*conj(Q).
    float Pr, Pi, Qr, Qi;
    upk(vP, Pr, Pi); upk(vQ, Qr, Qi);
    float p2 = fmaf(Pr, Pr, Pi * Pi);
    float q2 = fmaf(Qr, Qr, Qi * Qi);
    float nr = fmaf(Pr, Qr,  Pi * Qi);
    float ni = fmaf(Pi, Qr, -Pr * Qi);
    float dlr = (log10f(p2) - log10f(q2)) - log10f(omu) - log10f(obs_rhoa[fi]);
    float ph  = atan2f(ni, nr) * RAD2DEG_F;
    float dp  = ph - obs_phase[fi];
    float er = dlr * dlr;
    float ep = dp * dp;

    // ---- deterministic block reduction (4 warps) ----
    #pragma unroll
    for (int o = 16; o > 0; o >>= 1) {
        er += __shfl_down_sync(0xFFFFFFFFu, er, o);
        ep += __shfl_down_sync(0xFFFFFFFFu, ep, o);
    }
    __shared__ float red[8];
    __shared__ bool amLast;
    int lane = tid & 31, warp = tid >> 5;
    if (lane == 0) { red[warp * 2] = er; red[warp * 2 + 1] = ep; }
    __syncthreads();
    if (tid == 0) {
        g_part_rhoa[blockIdx.x]  = (red[0] + red[2]) + (red[4] + red[6]);
        g_part_phase[blockIdx.x] = (red[1] + red[3]) + (red[5] + red[7]);
        __threadfence();
        unsigned int prev = atomicInc(&g_count, NBLK - 1);  // wraps to 0 each run
        amLast = (prev == NBLK - 1);
    }
    __syncthreads();

    // ---- last block performs the final fixed-order reduction ----
    if (amLast) {
        float fr = g_part_rhoa[tid];     // NBLK == BLK == 128
        float fp = g_part_phase[tid];
        #pragma unroll
        for (int o = 16; o > 0; o >>= 1) {
            fr += __shfl_down_sync(0xFFFFFFFFu, fr, o);
            fp += __shfl_down_sync(0xFFFFFFFFu, fp, o);
        }
        if (lane == 0) { red[warp * 2] = fr; red[warp * 2 + 1] = fp; }
        __syncthreads();
        if (tid == 0) {
            float sr = (red[0] + red[2]) + (red[4] + red[6]);
            float sp = (red[1] + red[3]) + (red[5] + red[7]);
            float lr = sr * (1.0f / (float)NF);
            float lp = sp * (1.0f / (float)NF);
            out[0] = lr + 10.0f * lp;   // LAMBDA_RHOA=1, LAMBDA_PHASE=10
            out[1] = lr;
            out[2] = lp;
        }
    }
}

extern "C" void kernel_launch(void* const* d_in, const int* in_sizes, int n_in,
                              void* d_out, int out_size) {
    const float* rho       = (const float*)d_in[0];
    const float* thick     = (const float*)d_in[1];
    const float* freq      = (const float*)d_in[2];
    const float* obs_rhoa  = (const float*)d_in[3];
    const float* obs_phase = (const float*)d_in[4];
    float* out = (float*)d_out;

    mt_fused_kernel<<<NBLK, BLK>>>(rho, thick, freq, obs_rhoa, obs_phase, out);
}

// round 17
// speedup vs baseline: 1.5711x; 1.5711x over previous
#include <cuda_runtime.h>
#include <math.h>

// MTPhysicsLoss: 1D MT forward + misfit loss, single fused kernel (scalar FFMA).
//
// Projective recursion (no division on chain):
//   P' = A*P + B*Q ; Q' = C*P + A*Q   (complex), Z = P/Q
//   A = Zj(1-E), B = 2a^2 i (1+E), C = (1+E), Zj = a(1+i), a = s*sqrt(rho/2)
//   E = e^{-x}(cos x - i sin x), x = s*sqrt(2)*t/sqrt(rho), s = sqrt(omega*mu)
//
// R6 lesson: packed f32x2 regressed (serial 4-deep 64b nest + pack MOVs on the
// recurrence, <=1 warp/SMSP so nothing hides it). Scalar FFMAs with BALANCED
// 2-deep trees (8 independent streams/step) instead. Reduction fused via
// last-block-done (atomicInc wrap => graph-replay safe; fixed-order => deterministic).

#define NZ   256
#define NF   16384
#define BLK  128
#define NBLK (NF / BLK)   // 128 blocks, 1 freq/thread

#define MU_F        1.2566370614359173e-6f
#define TWO_PI_F    6.283185307179586f
#define INV_SQRT2_F 0.7071067811865476f
#define SQRT2_F     1.4142135623730951f
#define RAD2DEG_F   57.29577951308232f

__device__ float g_part_rhoa[NBLK];
__device__ float g_part_phase[NBLK];
__device__ unsigned int g_count = 0;

__device__ __forceinline__ float fast_rcp(float x) {
    float r; asm("rcp.approx.f32 %0, %1;" : "=f"(r) : "f"(x)); return r;
}

__global__ __launch_bounds__(BLK, 1)
void mt_fused_kernel(const float* __restrict__ rho,
                     const float* __restrict__ thick,
                     const float* __restrict__ freq,
                     const float* __restrict__ obs_rhoa,
                     const float* __restrict__ obs_phase,
                     float* __restrict__ out) {
    __shared__ float sh_h[NZ];       // sqrt(rho_j)/sqrt(2)     -> a = s*h
    __shared__ float sh_g[NZ - 1];   // sqrt(2)*t_j/sqrt(rho_j) -> x = s*g

    const int tid = threadIdx.x;

    #pragma unroll
    for (int j = tid; j < NZ; j += BLK) {
        float sr = sqrtf(rho[j]);
        sh_h[j] = sr * INV_SQRT2_F;
        if (j < NZ - 1) sh_g[j] = SQRT2_F * thick[j] * fast_rcp(sr);
    }
    __syncthreads();

    const int fi = blockIdx.x * BLK + tid;
    const float omu = TWO_PI_F * freq[fi] * MU_F;
    const float s   = sqrtf(omu);

    // Homogeneous state: P = Z0 = a0(1+i), Q = 1
    const float a0 = s * sh_h[NZ - 1];
    float Pr = a0, Pi = a0;
    float Qr = 1.0f, Qi = 0.0f;

    // 255 steps: 51 groups of 5 with one exact power-of-two renorm per group.
    for (int base = NZ - 2; base >= 4; base -= 5) {
        #pragma unroll
        for (int k = 0; k < 5; ++k) {
            const int j = base - k;
            // ---- coefficients (freq+layer only, off the P/Q chain) ----
            float a = s * sh_h[j];
            float x = s * sh_g[j];
            float e = __expf(-x);
            float sx, cx; __sincosf(x, &sx, &cx);
            float ecx = e * cx;          // Re(E)
            float esx = e * sx;          // -Im(E)
            float vr  = 1.0f + ecx;      // C = (vr, vi), vi = -esx
            float vi  = -esx;
            float w   = 1.0f - ecx;
            float Ar  = a * (w - esx);   // A = Zj(1-E)
            float Ai  = a * (w + esx);
            float a22 = 2.0f * (a * a);
            float Br  = a22 * esx;       // B = 2a^2 i (1+E)
            float Bi  = a22 * vr;

            // ---- update, balanced 2-deep trees (8 independent streams) ----
            float uPr = fmaf(Ar, Pr, -(Ai * Pi));   // Re(A*P)
            float vPr = fmaf(Br, Qr, -(Bi * Qi));   // Re(B*Q)
            float uPi = fmaf(Ar, Pi,  (Ai * Pr));   // Im(A*P)
            float vPi = fmaf(Br, Qi,  (Bi * Qr));   // Im(B*Q)
            float uQr = fmaf(vr, Pr, -(vi * Pi));   // Re(C*P)
            float vQr = fmaf(Ar, Qr, -(Ai * Qi));   // Re(A*Q)
            float uQi = fmaf(vr, Pi,  (vi * Pr));   // Im(C*P)
            float vQi = fmaf(Ar, Qi,  (Ai * Qr));   // Im(A*Q)
            Pr = uPr + vPr;
            Pi = uPi + vPi;
            Qr = uQr + vQr;
            Qi = uQi + vQi;
        }
        // Exact power-of-two renorm (no rounding): scale = 2^{-exponent(|Qr|+|Qi|)}
        float m = fabsf(Qr) + fabsf(Qi);
        int ebits = __float_as_int(m) & 0x7F800000;
        float scale = __int_as_float(0x7F000000 - ebits);
        Pr *= scale; Pi *= scale; Qr *= scale; Qi *= scale;
    }

    // Misfits: Z = P/Q. log10|Z|^2 = log10|P|^2 - log10|Q|^2; phase from P*conj(Q).
    float p2 = fmaf(Pr, Pr, Pi * Pi);
    float q2 = fmaf(Qr, Qr, Qi * Qi);
    float nr = fmaf(Pr, Qr,  Pi * Qi);
    float ni = fmaf(Pi, Qr, -Pr * Qi);
    float dlr = (log10f(p2) - log10f(q2)) - log10f(omu) - log10f(obs_rhoa[fi]);
    float ph  = atan2f(ni, nr) * RAD2DEG_F;
    float dp  = ph - obs_phase[fi];
    float er = dlr * dlr;
    float ep = dp * dp;

    // ---- deterministic block reduction (4 warps) ----
    #pragma unroll
    for (int o = 16; o > 0; o >>= 1) {
        er += __shfl_down_sync(0xFFFFFFFFu, er, o);
        ep += __shfl_down_sync(0xFFFFFFFFu, ep, o);
    }
    __shared__ float red[8];
    __shared__ bool amLast;
    int lane = tid & 31, warp = tid >> 5;
    if (lane == 0) { red[warp * 2] = er; red[warp * 2 + 1] = ep; }
    __syncthreads();
    if (tid == 0) {
        g_part_rhoa[blockIdx.x]  = (red[0] + red[2]) + (red[4] + red[6]);
        g_part_phase[blockIdx.x] = (red[1] + red[3]) + (red[5] + red[7]);
        __threadfence();
        unsigned int prev = atomicInc(&g_count, NBLK - 1);  // wraps to 0 each run
        amLast = (prev == NBLK - 1);
    }
    __syncthreads();

    // ---- last block performs the final fixed-order reduction ----
    if (amLast) {
        float fr = g_part_rhoa[tid];     // NBLK == BLK == 128
        float fp = g_part_phase[tid];
        #pragma unroll
        for (int o = 16; o > 0; o >>= 1) {
            fr += __shfl_down_sync(0xFFFFFFFFu, fr, o);
            fp += __shfl_down_sync(0xFFFFFFFFu, fp, o);
        }
        if (lane == 0) { red[warp * 2] = fr; red[warp * 2 + 1] = fp; }
        __syncthreads();
        if (tid == 0) {
            float sr = (red[0] + red[2]) + (red[4] + red[6]);
            float sp = (red[1] + red[3]) + (red[5] + red[7]);
            float lr = sr * (1.0f / (float)NF);
            float lp = sp * (1.0f / (float)NF);
            out[0] = lr + 10.0f * lp;   // LAMBDA_RHOA=1, LAMBDA_PHASE=10
            out[1] = lr;
            out[2] = lp;
        }
    }
}

extern "C" void kernel_launch(void* const* d_in, const int* in_sizes, int n_in,
                              void* d_out, int out_size) {
    const float* rho       = (const float*)d_in[0];
    const float* thick     = (const float*)d_in[1];
    const float* freq      = (const float*)d_in[2];
    const float* obs_rhoa  = (const float*)d_in[3];
    const float* obs_phase = (const float*)d_in[4];
    float* out = (float*)d_out;

    mt_fused_kernel<<<NBLK, BLK>>>(rho, thick, freq, obs_rhoa, obs_phase, out);
}